// round 6
// baseline (speedup 1.0000x reference)
#include <cuda_runtime.h>
#include <cuda_bf16.h>
#include <cstdint>

#define NN 50000
#define EE 800000
#define DD 128
#define NP1 (NN + 1)

// ---------------- device scratch (no allocation allowed) ----------------
__device__ float g_agg[(size_t)NN * DD];      // aggregated features
__device__ float g_h[(size_t)NN * DD];        // hidden layer output
__device__ int   g_ptr[NP1];                  // CSR row offsets by dst
__device__ int   g_cursor[NN];                // scatter cursors
__device__ int   g_src[EE];                   // normalized src ids (int32)
__device__ int   g_dst[EE];                   // normalized dst ids (int32)
__device__ int   g_src_sorted[EE];            // src ids sorted by dst
__device__ float g_inv_deg[NN];               // 1 / max(deg,1)
__device__ float g_WT[4 * DD * DD];           // transposed weights [k][o]
__device__ int   g_is32;                      // 1 if edge_index is int32

// ---------------- init: zero ptr histogram + dtype flag ----------------
__global__ void k_init() {
    int i = blockIdx.x * blockDim.x + threadIdx.x;
    if (i < NP1) g_ptr[i] = 0;
    if (i == 0) g_is32 = 0;
}

// ---------------- dtype probe ----------------
// If edge_index is int64 (values < 2^31), every odd 32-bit word of the first
// 2*E words is zero. If it is int32, the first 2*E words are the whole array
// and odd words are random ids (overwhelmingly nonzero). Reading 2*E words is
// in-bounds under BOTH interpretations.
__global__ void k_detect(const unsigned int* __restrict__ w) {
    int i = blockIdx.x * blockDim.x + threadIdx.x;
    if (i < EE) {
        if (w[2 * i + 1] != 0u) atomicOr(&g_is32, 1);
    }
}

// ---------------- normalize edges to int32 ----------------
__global__ void k_extract(const void* __restrict__ eiv) {
    int e = blockIdx.x * blockDim.x + threadIdx.x;
    if (e >= EE) return;
    int s, d;
    if (g_is32) {
        const int* p = (const int*)eiv;
        s = p[e]; d = p[EE + e];
    } else {
        const long long* p = (const long long*)eiv;
        s = (int)p[e]; d = (int)p[EE + e];
    }
    g_src[e] = s;
    g_dst[e] = d;
}

// ---------------- CSR build ----------------
__global__ void k_hist() {
    int e = blockIdx.x * blockDim.x + threadIdx.x;
    if (e < EE) atomicAdd(&g_ptr[g_dst[e] + 1], 1);
}

// single-block inclusive scan over g_ptr[0..NN] (counts at [dst+1] -> offsets)
__global__ void k_scan() {
    __shared__ int sh[1024];
    __shared__ int carry;
    int t = threadIdx.x;
    if (t == 0) carry = 0;
    __syncthreads();
    for (int base = 0; base < NP1; base += 1024) {
        int idx = base + t;
        int v = (idx < NP1) ? g_ptr[idx] : 0;
        sh[t] = v;
        __syncthreads();
        #pragma unroll
        for (int off = 1; off < 1024; off <<= 1) {
            int add = (t >= off) ? sh[t - off] : 0;
            __syncthreads();
            sh[t] += add;
            __syncthreads();
        }
        int c = carry;
        if (idx < NP1) g_ptr[idx] = sh[t] + c;
        __syncthreads();
        if (t == 1023) carry = c + sh[1023];
        __syncthreads();
    }
}

__global__ void k_deg_cursor() {
    int v = blockIdx.x * blockDim.x + threadIdx.x;
    if (v < NN) {
        int d = g_ptr[v + 1] - g_ptr[v];
        g_inv_deg[v] = 1.0f / (float)max(d, 1);
        g_cursor[v] = g_ptr[v];
    }
}

__global__ void k_scatter() {
    int e = blockIdx.x * blockDim.x + threadIdx.x;
    if (e < EE) {
        int pos = atomicAdd(&g_cursor[g_dst[e]], 1);
        g_src_sorted[pos] = g_src[e];
    }
}

// ---------------- weight transpose: WT[k*D+o] = W[o*D+k] ----------------
__global__ void k_transpose(const float* __restrict__ Wl0, const float* __restrict__ Wr0,
                            const float* __restrict__ Wl1, const float* __restrict__ Wr1) {
    int i = blockIdx.x * blockDim.x + threadIdx.x;   // 0 .. 4*128*128
    if (i >= 4 * DD * DD) return;
    int m = i >> 14;
    int r = (i >> 7) & 127;
    int c = i & 127;
    const float* W = (m == 0) ? Wl0 : (m == 1) ? Wr0 : (m == 2) ? Wl1 : Wr1;
    g_WT[m * DD * DD + c * DD + r] = W[r * DD + c];
}

// ---------------- segment-mean aggregation: one warp per dst node ----------------
__global__ void k_agg(const float* __restrict__ in, float* __restrict__ out) {
    int w = (blockIdx.x * blockDim.x + threadIdx.x) >> 5;
    if (w >= NN) return;
    int lane = threadIdx.x & 31;
    int beg = g_ptr[w], end = g_ptr[w + 1];
    float4 acc = make_float4(0.f, 0.f, 0.f, 0.f);
    int e = beg;
    for (; e + 1 < end; e += 2) {
        int s0 = g_src_sorted[e];
        int s1 = g_src_sorted[e + 1];
        float4 a = __ldg((const float4*)(in + (size_t)s0 * DD) + lane);
        float4 b = __ldg((const float4*)(in + (size_t)s1 * DD) + lane);
        acc.x += a.x + b.x; acc.y += a.y + b.y;
        acc.z += a.z + b.z; acc.w += a.w + b.w;
    }
    if (e < end) {
        int s0 = g_src_sorted[e];
        float4 a = __ldg((const float4*)(in + (size_t)s0 * DD) + lane);
        acc.x += a.x; acc.y += a.y; acc.z += a.z; acc.w += a.w;
    }
    float inv = g_inv_deg[w];
    float4 r = make_float4(acc.x * inv, acc.y * inv, acc.z * inv, acc.w * inv);
    *((float4*)(out + (size_t)w * DD) + lane) = r;
}

// ---------------- fused dual GEMM: out = A1@WT1 + A2@WT2 + b (optional relu) ----------------
// BM=64 rows, BN=128 cols (full), BK=16. 256 threads; thread = 8x4 outputs.
__global__ void __launch_bounds__(256)
k_gemm(const float* __restrict__ A1, const float* __restrict__ A2,
       const float* __restrict__ WT1, const float* __restrict__ WT2,
       const float* __restrict__ bias, float* __restrict__ out, int relu) {
    __shared__ float As[16][64];
    __shared__ float Bs[16][128];

    int block_row = blockIdx.x * 64;
    int t  = threadIdx.x;
    int ty = t >> 5;   // 0..7 : row group (8 rows each)
    int tx = t & 31;   // 0..31: col group (4 cols each)

    float acc[8][4];
    #pragma unroll
    for (int i = 0; i < 8; i++)
        #pragma unroll
        for (int j = 0; j < 4; j++) acc[i][j] = 0.f;

    int arow = t >> 2;            // 0..63
    int acg  = (t & 3) * 4;       // 0,4,8,12
    int grow = block_row + arow;
    bool a_ok = (grow < NN);

    #pragma unroll
    for (int half = 0; half < 2; half++) {
        const float* A  = half ? A2  : A1;
        const float* WT = half ? WT2 : WT1;
        for (int kk = 0; kk < DD; kk += 16) {
            // load A tile 64x16 (transposed into As)
            float4 v = a_ok ? *(const float4*)(A + (size_t)grow * DD + kk + acg)
                            : make_float4(0.f, 0.f, 0.f, 0.f);
            As[acg + 0][arow] = v.x;
            As[acg + 1][arow] = v.y;
            As[acg + 2][arow] = v.z;
            As[acg + 3][arow] = v.w;
            // load B tile 16x128
            #pragma unroll
            for (int i = 0; i < 2; i++) {
                int f = t + i * 256;          // 0..511
                int k = f >> 5;
                int c = (f & 31) * 4;
                *(float4*)&Bs[k][c] = *(const float4*)(WT + (size_t)(kk + k) * DD + c);
            }
            __syncthreads();
            #pragma unroll
            for (int k = 0; k < 16; k++) {
                float a[8], b[4];
                #pragma unroll
                for (int i = 0; i < 8; i++) a[i] = As[k][ty * 8 + i];
                #pragma unroll
                for (int j = 0; j < 4; j++) b[j] = Bs[k][tx * 4 + j];
                #pragma unroll
                for (int i = 0; i < 8; i++)
                    #pragma unroll
                    for (int j = 0; j < 4; j++) acc[i][j] += a[i] * b[j];
            }
            __syncthreads();
        }
    }

    float b4[4];
    #pragma unroll
    for (int j = 0; j < 4; j++) b4[j] = bias[tx * 4 + j];

    #pragma unroll
    for (int i = 0; i < 8; i++) {
        int n = block_row + ty * 8 + i;
        if (n < NN) {
            #pragma unroll
            for (int j = 0; j < 4; j++) {
                float v = acc[i][j] + b4[j];
                if (relu) v = fmaxf(v, 0.f);
                out[(size_t)n * DD + tx * 4 + j] = v;
            }
        }
    }
}

// ---------------- host launcher ----------------
extern "C" void kernel_launch(void* const* d_in, const int* in_sizes, int n_in,
                              void* d_out, int out_size) {
    const float* x   = (const float*)d_in[0];
    const void*  ei  = d_in[1];                 // int32 or int64 — probed on device
    const float* Wl0 = (const float*)d_in[2];
    const float* Wr0 = (const float*)d_in[3];
    const float* b0  = (const float*)d_in[4];
    const float* Wl1 = (const float*)d_in[5];
    const float* Wr1 = (const float*)d_in[6];
    const float* b1  = (const float*)d_in[7];
    float*       out = (float*)d_out;

    float* agg; cudaGetSymbolAddress((void**)&agg, g_agg);
    float* h;   cudaGetSymbolAddress((void**)&h,   g_h);
    float* WT;  cudaGetSymbolAddress((void**)&WT,  g_WT);
    const float* WTl0 = WT + 0 * DD * DD;
    const float* WTr0 = WT + 1 * DD * DD;
    const float* WTl1 = WT + 2 * DD * DD;
    const float* WTr1 = WT + 3 * DD * DD;

    // dtype probe + edge normalization + CSR build (dst-sorted), reused by both layers
    k_init<<<(NP1 + 255) / 256, 256>>>();
    k_detect<<<(EE + 255) / 256, 256>>>((const unsigned int*)ei);
    k_extract<<<(EE + 255) / 256, 256>>>(ei);
    k_hist<<<(EE + 255) / 256, 256>>>();
    k_scan<<<1, 1024>>>();
    k_deg_cursor<<<(NN + 255) / 256, 256>>>();
    k_scatter<<<(EE + 255) / 256, 256>>>();
    k_transpose<<<(4 * DD * DD + 255) / 256, 256>>>(Wl0, Wr0, Wl1, Wr1);

    const int gemm_blocks = (NN + 63) / 64;
    const int agg_blocks  = (NN + 7) / 8;   // 8 warps per block

    // layer 0: h = relu(agg(x)@Wl0^T + x@Wr0^T + b0)
    k_agg<<<agg_blocks, 256>>>(x, agg);
    k_gemm<<<gemm_blocks, 256>>>(agg, x, WTl0, WTr0, b0, h, 1);

    // layer 1: out = agg(h)@Wl1^T + h@Wr1^T + b1
    k_agg<<<agg_blocks, 256>>>(h, agg);
    k_gemm<<<gemm_blocks, 256>>>(agg, h, WTl1, WTr1, b1, out, 0);
}

// round 7
// speedup vs baseline: 1.8319x; 1.8319x over previous
#include <cuda_runtime.h>
#include <cuda_bf16.h>
#include <cstdint>

#define NN 50000
#define EE 800000
#define DD 128
#define NP1 (NN + 1)
#define SCAN_BLOCKS 49   // ceil(50001/1024)

// ---------------- device scratch (no allocation allowed) ----------------
__device__ float g_agg[(size_t)NN * DD];      // aggregated features
__device__ float g_h[(size_t)NN * DD];        // hidden layer output
__device__ int   g_ptr[NP1];                  // CSR row offsets by dst
__device__ int   g_cursor[NN];                // scatter cursors
__device__ int   g_src_sorted[EE];            // src ids sorted by dst
__device__ float g_inv_deg[NN];               // 1 / max(deg,1)
__device__ int   g_bsum[64];                  // scan block partials
__device__ int   g_is32;                      // 1 if edge_index is int32
// bf16 hi/lo weight planes: [mat(4)][plane(2)][n=128][k=128]
__device__ __nv_bfloat16 g_Wbf[4 * 2 * DD * DD];

// ---------------- init ----------------
__global__ void k_init() {
    int i = blockIdx.x * blockDim.x + threadIdx.x;
    if (i < NP1) g_ptr[i] = 0;
    if (i == 0) g_is32 = 0;
}

// ---------------- dtype probe (1 block) ----------------
// int64 ids < 2^31 -> odd 32-bit words all zero. int32 -> odd words are random
// node ids (nonzero w.p. 1 - 1/50000 each). Probe 2048 odd words (word index
// < 4096, in-bounds under both interpretations of a 2*E-element array).
__global__ void k_detect(const unsigned int* __restrict__ w) {
    int t = threadIdx.x;
    int flag = 0;
    #pragma unroll
    for (int j = 0; j < 8; j++)
        if (w[2 * (t + 256 * j) + 1] != 0u) flag = 1;
    if (__syncthreads_or(flag) && t == 0) g_is32 = 1;
}

__device__ __forceinline__ void load_edge(const void* eiv, int e, int& s, int& d) {
    if (g_is32) {
        const int* p = (const int*)eiv;
        s = p[e]; d = p[EE + e];
    } else {
        const long long* p = (const long long*)eiv;
        s = (int)p[e]; d = (int)p[EE + e];
    }
}

// ---------------- CSR build ----------------
__global__ void k_hist(const void* __restrict__ eiv) {
    int e = blockIdx.x * blockDim.x + threadIdx.x;
    if (e < EE) {
        int s, d; load_edge(eiv, e, s, d);
        atomicAdd(&g_ptr[d + 1], 1);
    }
}

// multi-block scan: local inclusive scan + block totals
__global__ void k_scan1() {
    __shared__ int sh[1024];
    int t = threadIdx.x;
    int idx = blockIdx.x * 1024 + t;
    int v = (idx < NP1) ? g_ptr[idx] : 0;
    sh[t] = v;
    __syncthreads();
    #pragma unroll
    for (int off = 1; off < 1024; off <<= 1) {
        int add = (t >= off) ? sh[t - off] : 0;
        __syncthreads();
        sh[t] += add;
        __syncthreads();
    }
    if (idx < NP1) g_ptr[idx] = sh[t];
    if (t == 1023) g_bsum[blockIdx.x] = sh[1023];
}

// exclusive scan of 49 block totals (1 block, 64 threads)
__global__ void k_scan2() {
    __shared__ int sh[64];
    int t = threadIdx.x;
    sh[t] = (t < SCAN_BLOCKS) ? g_bsum[t] : 0;
    __syncthreads();
    #pragma unroll
    for (int off = 1; off < 64; off <<= 1) {
        int add = (t >= off) ? sh[t - off] : 0;
        __syncthreads();
        sh[t] += add;
        __syncthreads();
    }
    if (t < SCAN_BLOCKS) g_bsum[t] = (t == 0) ? 0 : sh[t - 1];
}

// add carries in place
__global__ void k_scan3() {
    int idx = blockIdx.x * 1024 + threadIdx.x;
    int b = idx >> 10;
    if (idx < NP1 && b > 0) g_ptr[idx] += g_bsum[b];
}

__global__ void k_deg_cursor() {
    int v = blockIdx.x * blockDim.x + threadIdx.x;
    if (v < NN) {
        int d = g_ptr[v + 1] - g_ptr[v];
        g_inv_deg[v] = 1.0f / (float)max(d, 1);
        g_cursor[v] = g_ptr[v];
    }
}

__global__ void k_scatter(const void* __restrict__ eiv) {
    int e = blockIdx.x * blockDim.x + threadIdx.x;
    if (e < EE) {
        int s, d; load_edge(eiv, e, s, d);
        int pos = atomicAdd(&g_cursor[d], 1);
        g_src_sorted[pos] = s;
    }
}

// ---------------- weight prep: fp32 W[n][k] -> bf16 hi/lo planes ----------------
__global__ void k_prep_w(const float* __restrict__ Wl0, const float* __restrict__ Wr0,
                         const float* __restrict__ Wl1, const float* __restrict__ Wr1) {
    int i = blockIdx.x * blockDim.x + threadIdx.x;   // 0 .. 4*128*128
    if (i >= 4 * DD * DD) return;
    int m = i >> 14;
    int rem = i & 16383;
    const float* W = (m == 0) ? Wl0 : (m == 1) ? Wr0 : (m == 2) ? Wl1 : Wr1;
    float v = W[rem];
    __nv_bfloat16 hi = __float2bfloat16(v);
    __nv_bfloat16 lo = __float2bfloat16(v - __bfloat162float(hi));
    g_Wbf[(size_t)(m * 2 + 0) * DD * DD + rem] = hi;
    g_Wbf[(size_t)(m * 2 + 1) * DD * DD + rem] = lo;
}

// ---------------- segment-mean aggregation: one warp per dst node ----------------
__global__ void k_agg(const float* __restrict__ in, float* __restrict__ out) {
    int w = (blockIdx.x * blockDim.x + threadIdx.x) >> 5;
    if (w >= NN) return;
    int lane = threadIdx.x & 31;
    int beg = g_ptr[w], end = g_ptr[w + 1];
    float4 acc = make_float4(0.f, 0.f, 0.f, 0.f);
    int e = beg;
    for (; e + 1 < end; e += 2) {
        int s0 = g_src_sorted[e];
        int s1 = g_src_sorted[e + 1];
        float4 a = __ldg((const float4*)(in + (size_t)s0 * DD) + lane);
        float4 b = __ldg((const float4*)(in + (size_t)s1 * DD) + lane);
        acc.x += a.x + b.x; acc.y += a.y + b.y;
        acc.z += a.z + b.z; acc.w += a.w + b.w;
    }
    if (e < end) {
        int s0 = g_src_sorted[e];
        float4 a = __ldg((const float4*)(in + (size_t)s0 * DD) + lane);
        acc.x += a.x; acc.y += a.y; acc.z += a.z; acc.w += a.w;
    }
    float inv = g_inv_deg[w];
    float4 r = make_float4(acc.x * inv, acc.y * inv, acc.z * inv, acc.w * inv);
    *((float4*)(out + (size_t)w * DD) + lane) = r;
}

// ---------------- tensor-core dual GEMM with bf16 hi/lo split ----------------
// out[n][o] = A1@B1^T + A2@B2^T + bias (optional relu), B given as [o][k] (= W).
// Block: 128 rows x 128 cols, 8 warps (4 m x 2 n), warp tile 32x64.
// mma.m16n8k16.row.col: A row-major [m][k], B "col-major" = [n][k] = W as-is.
// Per fp32 value: v = hi + lo (bf16); product via 3 MMAs (hihi + hilo + lohi).
#define MMA_BF16(acc, a, b)                                              \
    asm volatile(                                                        \
        "mma.sync.aligned.m16n8k16.row.col.f32.bf16.bf16.f32 "           \
        "{%0,%1,%2,%3}, {%4,%5,%6,%7}, {%8,%9}, {%0,%1,%2,%3};"          \
        : "+f"(acc[0]), "+f"(acc[1]), "+f"(acc[2]), "+f"(acc[3])         \
        : "r"(a[0]), "r"(a[1]), "r"(a[2]), "r"(a[3]), "r"(b[0]), "r"(b[1]))

__global__ void __launch_bounds__(256)
k_gemm(const float* __restrict__ A1, const float* __restrict__ A2,
       const __nv_bfloat16* __restrict__ B1,   // [2][128][128] hi/lo planes
       const __nv_bfloat16* __restrict__ B2,
       const float* __restrict__ bias, float* __restrict__ out, int relu) {
    __shared__ __nv_bfloat16 As[2][128][40];   // [plane][m][k] pad 40 (conflict-free)
    __shared__ __nv_bfloat16 Bs[2][128][40];   // [plane][n][k]

    int t = threadIdx.x;
    int block_row = blockIdx.x * 128;
    int wid = t >> 5, lane = t & 31;
    int wm = (wid & 3) * 32;                   // warp row offset
    int wn = (wid >> 2) * 64;                  // warp col offset
    int fr = lane >> 2, fc = lane & 3;         // fragment row/col lane decomposition

    float acc[2][8][4];
    #pragma unroll
    for (int mi = 0; mi < 2; mi++)
        #pragma unroll
        for (int ni = 0; ni < 8; ni++)
            #pragma unroll
            for (int q = 0; q < 4; q++) acc[mi][ni][q] = 0.f;

    // A global-load mapping: thread -> (row group of 4, 4 consecutive k)
    int ar = t >> 3, ac = (t & 7) * 4;         // ar 0..31, ac 0,4,..,28
    // B global-load mapping: 2 threads per n-row, 16 k each
    int bn = t >> 1, bseg = (t & 1) * 16;

    #pragma unroll
    for (int half = 0; half < 2; half++) {
        const float* A = half ? A2 : A1;
        const __nv_bfloat16* B = half ? B2 : B1;
        for (int kc = 0; kc < 4; kc++) {
            int k0 = kc * 32;
            // ---- load + split A chunk 128x32 ----
            #pragma unroll
            for (int g = 0; g < 4; g++) {
                int row = ar + g * 32;
                int gr = block_row + row;
                float4 v = (gr < NN) ? __ldg((const float4*)(A + (size_t)gr * DD + k0 + ac))
                                     : make_float4(0.f, 0.f, 0.f, 0.f);
                __nv_bfloat16 h0 = __float2bfloat16(v.x);
                __nv_bfloat16 h1 = __float2bfloat16(v.y);
                __nv_bfloat16 h2 = __float2bfloat16(v.z);
                __nv_bfloat16 h3 = __float2bfloat16(v.w);
                __nv_bfloat16 l0 = __float2bfloat16(v.x - __bfloat162float(h0));
                __nv_bfloat16 l1 = __float2bfloat16(v.y - __bfloat162float(h1));
                __nv_bfloat16 l2 = __float2bfloat16(v.z - __bfloat162float(h2));
                __nv_bfloat16 l3 = __float2bfloat16(v.w - __bfloat162float(h3));
                __nv_bfloat162 hp0 = __halves2bfloat162(h0, h1);
                __nv_bfloat162 hp1 = __halves2bfloat162(h2, h3);
                __nv_bfloat162 lp0 = __halves2bfloat162(l0, l1);
                __nv_bfloat162 lp1 = __halves2bfloat162(l2, l3);
                *(__nv_bfloat162*)&As[0][row][ac]     = hp0;
                *(__nv_bfloat162*)&As[0][row][ac + 2] = hp1;
                *(__nv_bfloat162*)&As[1][row][ac]     = lp0;
                *(__nv_bfloat162*)&As[1][row][ac + 2] = lp1;
            }
            // ---- load B chunk 128x32 (both planes, pre-split bf16) ----
            #pragma unroll
            for (int p = 0; p < 2; p++) {
                const uint4* src = (const uint4*)(B + (size_t)p * DD * DD +
                                                  (size_t)bn * DD + k0 + bseg);
                uint4 u0 = __ldg(src);
                uint4 u1 = __ldg(src + 1);
                *(uint4*)&Bs[p][bn][bseg]     = u0;
                *(uint4*)&Bs[p][bn][bseg + 8] = u1;
            }
            __syncthreads();
            // ---- compute: two k16 steps ----
            #pragma unroll
            for (int ks = 0; ks < 2; ks++) {
                int kk = ks * 16;
                uint32_t af[2][2][4];   // [mi][plane][reg]
                #pragma unroll
                for (int mi = 0; mi < 2; mi++)
                    #pragma unroll
                    for (int p = 0; p < 2; p++) {
                        int row = wm + mi * 16;
                        af[mi][p][0] = *(const uint32_t*)&As[p][row + fr][kk + 2 * fc];
                        af[mi][p][1] = *(const uint32_t*)&As[p][row + fr + 8][kk + 2 * fc];
                        af[mi][p][2] = *(const uint32_t*)&As[p][row + fr][kk + 2 * fc + 8];
                        af[mi][p][3] = *(const uint32_t*)&As[p][row + fr + 8][kk + 2 * fc + 8];
                    }
                uint32_t bf[8][2][2];   // [ni][plane][reg]
                #pragma unroll
                for (int ni = 0; ni < 8; ni++)
                    #pragma unroll
                    for (int p = 0; p < 2; p++) {
                        int col = wn + ni * 8 + fr;
                        bf[ni][p][0] = *(const uint32_t*)&Bs[p][col][kk + 2 * fc];
                        bf[ni][p][1] = *(const uint32_t*)&Bs[p][col][kk + 2 * fc + 8];
                    }
                #pragma unroll
                for (int mi = 0; mi < 2; mi++)
                    #pragma unroll
                    for (int ni = 0; ni < 8; ni++) {
                        MMA_BF16(acc[mi][ni], af[mi][0], bf[ni][0]);  // hi*hi
                        MMA_BF16(acc[mi][ni], af[mi][0], bf[ni][1]);  // hi*lo
                        MMA_BF16(acc[mi][ni], af[mi][1], bf[ni][0]);  // lo*hi
                    }
            }
            __syncthreads();
        }
    }

    // ---- epilogue: bias (+relu), store float2 per fragment row ----
    #pragma unroll
    for (int mi = 0; mi < 2; mi++) {
        #pragma unroll
        for (int ni = 0; ni < 8; ni++) {
            int col = wn + ni * 8 + 2 * fc;
            float bv0 = __ldg(&bias[col]);
            float bv1 = __ldg(&bias[col + 1]);
            int row0 = block_row + wm + mi * 16 + fr;
            float v0 = acc[mi][ni][0] + bv0;
            float v1 = acc[mi][ni][1] + bv1;
            float v2 = acc[mi][ni][2] + bv0;
            float v3 = acc[mi][ni][3] + bv1;
            if (relu) {
                v0 = fmaxf(v0, 0.f); v1 = fmaxf(v1, 0.f);
                v2 = fmaxf(v2, 0.f); v3 = fmaxf(v3, 0.f);
            }
            if (row0 < NN)
                *(float2*)&out[(size_t)row0 * DD + col] = make_float2(v0, v1);
            if (row0 + 8 < NN)
                *(float2*)&out[(size_t)(row0 + 8) * DD + col] = make_float2(v2, v3);
        }
    }
}

// ---------------- host launcher ----------------
extern "C" void kernel_launch(void* const* d_in, const int* in_sizes, int n_in,
                              void* d_out, int out_size) {
    const float* x   = (const float*)d_in[0];
    const void*  ei  = d_in[1];                 // int32 or int64 — probed on device
    const float* Wl0 = (const float*)d_in[2];
    const float* Wr0 = (const float*)d_in[3];
    const float* b0  = (const float*)d_in[4];
    const float* Wl1 = (const float*)d_in[5];
    const float* Wr1 = (const float*)d_in[6];
    const float* b1  = (const float*)d_in[7];
    float*       out = (float*)d_out;

    float* agg; cudaGetSymbolAddress((void**)&agg, g_agg);
    float* h;   cudaGetSymbolAddress((void**)&h,   g_h);
    __nv_bfloat16* Wbf; cudaGetSymbolAddress((void**)&Wbf, g_Wbf);
    const __nv_bfloat16* Bl0 = Wbf + (size_t)0 * 2 * DD * DD;  // Wl0 hi/lo
    const __nv_bfloat16* Br0 = Wbf + (size_t)1 * 2 * DD * DD;  // Wr0 hi/lo
    const __nv_bfloat16* Bl1 = Wbf + (size_t)2 * 2 * DD * DD;  // Wl1 hi/lo
    const __nv_bfloat16* Br1 = Wbf + (size_t)3 * 2 * DD * DD;  // Wr1 hi/lo

    // dtype probe + CSR build (dst-sorted) + weight prep, reused by both layers
    k_init<<<(NP1 + 255) / 256, 256>>>();
    k_detect<<<1, 256>>>((const unsigned int*)ei);
    k_hist<<<(EE + 255) / 256, 256>>>(ei);
    k_scan1<<<SCAN_BLOCKS, 1024>>>();
    k_scan2<<<1, 64>>>();
    k_scan3<<<SCAN_BLOCKS, 1024>>>();
    k_deg_cursor<<<(NN + 255) / 256, 256>>>();
    k_scatter<<<(EE + 255) / 256, 256>>>(ei);
    k_prep_w<<<(4 * DD * DD + 255) / 256, 256>>>(Wl0, Wr0, Wl1, Wr1);

    const int gemm_blocks = (NN + 127) / 128;
    const int agg_blocks  = (NN + 7) / 8;   // 8 warps per block

    // layer 0: h = relu(agg(x)@Wl0^T + x@Wr0^T + b0)
    k_agg<<<agg_blocks, 256>>>(x, agg);
    k_gemm<<<gemm_blocks, 256>>>(agg, x, Bl0, Br0, b0, h, 1);

    // layer 1: out = agg(h)@Wl1^T + h@Wr1^T + b1
    k_agg<<<agg_blocks, 256>>>(h, agg);
    k_gemm<<<gemm_blocks, 256>>>(agg, h, Bl1, Br1, b1, out, 0);
}

// round 10
// speedup vs baseline: 1.8944x; 1.0341x over previous
#include <cuda_runtime.h>
#include <cuda_bf16.h>
#include <cstdint>

#define NN 50000
#define EE 800000
#define DD 128
#define NP1 (NN + 1)
#define SCAN_BLOCKS 49            // ceil(50001/1024)
#define PTRSZ (SCAN_BLOCKS * 1024) // padded histogram/scan region (50176)

// ---------------- device scratch (no allocation allowed) ----------------
__device__ float g_agg[(size_t)NN * DD];      // aggregated features
__device__ float g_h[(size_t)NN * DD];        // hidden layer output
__device__ int   g_ptr[PTRSZ + 4];            // histogram / raw scan (padded, zeroed)
__device__ int   g_ptrF[NP1];                 // final CSR offsets
__device__ int   g_cursor[NN];                // scatter cursors
__device__ int   g_src_sorted[EE];            // src ids sorted by dst
__device__ float g_inv_deg[NN];               // 1 / max(deg,1)
__device__ int   g_bsum[64];                  // scan block partials
__device__ int   g_is32;                      // 1 if edge_index is int32
// bf16 hi/lo weight planes: [mat(4)][plane(2)][n=128][k=128]
__device__ __nv_bfloat16 g_Wbf[4 * 2 * DD * DD];

// ---------------- weight prep + dtype probe (block 0) ----------------
// prep: fp32 W[n][k] -> bf16 hi/lo planes. 256 blocks x 256 = 65536 = 4*128*128.
// probe: int64 ids < 2^31 -> odd 32-bit words all zero; int32 -> odd words are
// random node ids (nonzero w.p. 1-1/50000). 2048 probed words decide it.
__global__ void k_pre(const float* __restrict__ Wl0, const float* __restrict__ Wr0,
                      const float* __restrict__ Wl1, const float* __restrict__ Wr1,
                      const unsigned int* __restrict__ w) {
    int i = blockIdx.x * 256 + threadIdx.x;
    int m = i >> 14;
    int rem = i & 16383;
    const float* W = (m == 0) ? Wl0 : (m == 1) ? Wr0 : (m == 2) ? Wl1 : Wr1;
    float v = W[rem];
    __nv_bfloat16 hi = __float2bfloat16(v);
    __nv_bfloat16 lo = __float2bfloat16(v - __bfloat162float(hi));
    g_Wbf[(size_t)(m * 2 + 0) * DD * DD + rem] = hi;
    g_Wbf[(size_t)(m * 2 + 1) * DD * DD + rem] = lo;
    if (blockIdx.x == 0) {
        int t = threadIdx.x;
        int flag = 0;
        #pragma unroll
        for (int j = 0; j < 8; j++)
            if (w[2 * (t + 256 * j) + 1] != 0u) flag = 1;
        int r = __syncthreads_or(flag);
        if (t == 0) g_is32 = r ? 1 : 0;
    }
}

// ---------------- CSR build (2 edges per thread) ----------------
__global__ void k_hist(const void* __restrict__ eiv) {
    int e2 = (blockIdx.x * blockDim.x + threadIdx.x) * 2;
    if (e2 >= EE) return;
    int d0, d1;
    if (g_is32) {
        const int2 dd = *(const int2*)((const int*)eiv + EE + e2);
        d0 = dd.x; d1 = dd.y;
    } else {
        const longlong2 dd = *(const longlong2*)((const long long*)eiv + EE + e2);
        d0 = (int)dd.x; d1 = (int)dd.y;
    }
    atomicAdd(&g_ptr[d0 + 1], 1);
    atomicAdd(&g_ptr[d1 + 1], 1);
}

// shuffle-based block-inclusive scan: 49 blocks x 256 threads x 4 elems
__global__ void k_scan1() {
    __shared__ int wsum[8];
    int t = threadIdx.x, lane = t & 31, wp = t >> 5;
    int base = blockIdx.x * 1024 + t * 4;
    int4 v = *(const int4*)&g_ptr[base];
    v.y += v.x; v.z += v.y; v.w += v.z;
    int s = v.w;
    #pragma unroll
    for (int off = 1; off < 32; off <<= 1) {
        int n = __shfl_up_sync(0xffffffffu, s, off);
        if (lane >= off) s += n;
    }
    if (lane == 31) wsum[wp] = s;
    __syncthreads();
    if (t < 8) {
        int x = wsum[t];
        #pragma unroll
        for (int off = 1; off < 8; off <<= 1) {
            int n = __shfl_up_sync(0xffu, x, off);
            if (t >= off) x += n;
        }
        wsum[t] = x;
    }
    __syncthreads();
    int add = (wp ? wsum[wp - 1] : 0) + (s - v.w);
    v.x += add; v.y += add; v.z += add; v.w += add;
    *(int4*)&g_ptr[base] = v;
    if (t == 255) g_bsum[blockIdx.x] = v.w;
}

// exclusive scan of 49 block totals
__global__ void k_scan2() {
    __shared__ int sh[64];
    int t = threadIdx.x;
    sh[t] = (t < SCAN_BLOCKS) ? g_bsum[t] : 0;
    __syncthreads();
    #pragma unroll
    for (int off = 1; off < 64; off <<= 1) {
        int add = (t >= off) ? sh[t - off] : 0;
        __syncthreads();
        sh[t] += add;
        __syncthreads();
    }
    if (t < SCAN_BLOCKS) g_bsum[t] = (t == 0) ? 0 : sh[t - 1];
}

// add carries -> final offsets (g_ptrF) + degree + cursor, fused
__global__ void k_scan3() {
    int idx = blockIdx.x * blockDim.x + threadIdx.x;
    if (idx >= NP1) return;
    int fin = g_ptr[idx] + g_bsum[idx >> 10];
    g_ptrF[idx] = fin;
    if (idx < NN) {
        int fin1 = g_ptr[idx + 1] + g_bsum[(idx + 1) >> 10];
        int d = fin1 - fin;
        g_inv_deg[idx] = 1.0f / (float)max(d, 1);
        g_cursor[idx] = fin;
    }
}

__global__ void k_scatter(const void* __restrict__ eiv) {
    int e2 = (blockIdx.x * blockDim.x + threadIdx.x) * 2;
    if (e2 >= EE) return;
    int s0, s1, d0, d1;
    if (g_is32) {
        const int* p = (const int*)eiv;
        const int2 ss = *(const int2*)(p + e2);
        const int2 dd = *(const int2*)(p + EE + e2);
        s0 = ss.x; s1 = ss.y; d0 = dd.x; d1 = dd.y;
    } else {
        const long long* p = (const long long*)eiv;
        const longlong2 ss = *(const longlong2*)(p + e2);
        const longlong2 dd = *(const longlong2*)(p + EE + e2);
        s0 = (int)ss.x; s1 = (int)ss.y; d0 = (int)dd.x; d1 = (int)dd.y;
    }
    int p0 = atomicAdd(&g_cursor[d0], 1);
    g_src_sorted[p0] = s0;
    int p1 = atomicAdd(&g_cursor[d1], 1);
    g_src_sorted[p1] = s1;
}

// ---------------- segment-mean aggregation: one warp per dst node ----------------
__global__ void k_agg(const float* __restrict__ in, float* __restrict__ out) {
    int w = (blockIdx.x * blockDim.x + threadIdx.x) >> 5;
    if (w >= NN) return;
    int lane = threadIdx.x & 31;
    int beg = g_ptrF[w], end = g_ptrF[w + 1];
    float4 acc = make_float4(0.f, 0.f, 0.f, 0.f);
    int e = beg;
    for (; e + 3 < end; e += 4) {
        int s0 = g_src_sorted[e];
        int s1 = g_src_sorted[e + 1];
        int s2 = g_src_sorted[e + 2];
        int s3 = g_src_sorted[e + 3];
        float4 a = __ldg((const float4*)(in + (size_t)s0 * DD) + lane);
        float4 b = __ldg((const float4*)(in + (size_t)s1 * DD) + lane);
        float4 c = __ldg((const float4*)(in + (size_t)s2 * DD) + lane);
        float4 d = __ldg((const float4*)(in + (size_t)s3 * DD) + lane);
        acc.x += (a.x + b.x) + (c.x + d.x);
        acc.y += (a.y + b.y) + (c.y + d.y);
        acc.z += (a.z + b.z) + (c.z + d.z);
        acc.w += (a.w + b.w) + (c.w + d.w);
    }
    for (; e < end; e++) {
        int s0 = g_src_sorted[e];
        float4 a = __ldg((const float4*)(in + (size_t)s0 * DD) + lane);
        acc.x += a.x; acc.y += a.y; acc.z += a.z; acc.w += a.w;
    }
    float inv = g_inv_deg[w];
    float4 r = make_float4(acc.x * inv, acc.y * inv, acc.z * inv, acc.w * inv);
    *((float4*)(out + (size_t)w * DD) + lane) = r;
}

// ---------------- tensor-core dual GEMM with bf16 hi/lo split ----------------
// out = A1@B1^T + A2@B2^T + bias (optional relu); B given as [o][k] (= W).
// Block 128x128, 8 warps (4m x 2n), warp tile 32x64, mma.m16n8k16.row.col.
// fp32 value v = hi + lo (bf16); product via 3 MMAs (hihi + hilo + lohi).
// One-phase register prefetch: chunk p+1 global loads overlap chunk p MMAs.
#define MMA_BF16(acc, a, b)                                              \
    asm volatile(                                                        \
        "mma.sync.aligned.m16n8k16.row.col.f32.bf16.bf16.f32 "           \
        "{%0,%1,%2,%3}, {%4,%5,%6,%7}, {%8,%9}, {%0,%1,%2,%3};"          \
        : "+f"(acc[0]), "+f"(acc[1]), "+f"(acc[2]), "+f"(acc[3])         \
        : "r"(a[0]), "r"(a[1]), "r"(a[2]), "r"(a[3]), "r"(b[0]), "r"(b[1]))

__global__ void __launch_bounds__(256)
k_gemm(const float* __restrict__ A1, const float* __restrict__ A2,
       const __nv_bfloat16* __restrict__ B1,   // [2][128][128] hi/lo planes
       const __nv_bfloat16* __restrict__ B2,
       const float* __restrict__ bias, float* __restrict__ out, int relu) {
    __shared__ __nv_bfloat16 As[2][128][40];   // [plane][m][k] pad 40 (conflict-free)
    __shared__ __nv_bfloat16 Bs[2][128][40];   // [plane][n][k]

    int t = threadIdx.x;
    int block_row = blockIdx.x * 128;
    int wid = t >> 5, lane = t & 31;
    int wm = (wid & 3) * 32;                   // warp row offset
    int wn = (wid >> 2) * 64;                  // warp col offset
    int fr = lane >> 2, fc = lane & 3;

    float acc[2][8][4];
    #pragma unroll
    for (int mi = 0; mi < 2; mi++)
        #pragma unroll
        for (int ni = 0; ni < 8; ni++)
            #pragma unroll
            for (int q = 0; q < 4; q++) acc[mi][ni][q] = 0.f;

    // A global-load mapping: thread -> (4 row groups, 4 consecutive k)
    int ar = t >> 3, ac = (t & 7) * 4;
    // B global-load mapping: 2 threads per n-row, 16 k each
    int bn = t >> 1, bseg = (t & 1) * 16;

    int grow[4]; bool aok[4];
    #pragma unroll
    for (int g = 0; g < 4; g++) {
        grow[g] = block_row + ar + g * 32;
        aok[g] = grow[g] < NN;
    }

    float4 ra[4];
    uint4  rb[4];

    // prefetch phase 0 (half 0, kc 0)
    #pragma unroll
    for (int g = 0; g < 4; g++)
        ra[g] = aok[g] ? __ldg((const float4*)(A1 + (size_t)grow[g] * DD + ac))
                       : make_float4(0.f, 0.f, 0.f, 0.f);
    #pragma unroll
    for (int pl = 0; pl < 2; pl++) {
        const uint4* src = (const uint4*)(B1 + (size_t)pl * DD * DD + (size_t)bn * DD + bseg);
        rb[pl * 2 + 0] = __ldg(src);
        rb[pl * 2 + 1] = __ldg(src + 1);
    }

    #pragma unroll 1
    for (int p = 0; p < 8; p++) {
        // ---- store current regs to smem (A with on-the-fly hi/lo split) ----
        #pragma unroll
        for (int g = 0; g < 4; g++) {
            int row = ar + g * 32;
            float4 v = ra[g];
            __nv_bfloat16 h0 = __float2bfloat16(v.x);
            __nv_bfloat16 h1 = __float2bfloat16(v.y);
            __nv_bfloat16 h2 = __float2bfloat16(v.z);
            __nv_bfloat16 h3 = __float2bfloat16(v.w);
            __nv_bfloat16 l0 = __float2bfloat16(v.x - __bfloat162float(h0));
            __nv_bfloat16 l1 = __float2bfloat16(v.y - __bfloat162float(h1));
            __nv_bfloat16 l2 = __float2bfloat16(v.z - __bfloat162float(h2));
            __nv_bfloat16 l3 = __float2bfloat16(v.w - __bfloat162float(h3));
            *(__nv_bfloat162*)&As[0][row][ac]     = __halves2bfloat162(h0, h1);
            *(__nv_bfloat162*)&As[0][row][ac + 2] = __halves2bfloat162(h2, h3);
            *(__nv_bfloat162*)&As[1][row][ac]     = __halves2bfloat162(l0, l1);
            *(__nv_bfloat162*)&As[1][row][ac + 2] = __halves2bfloat162(l2, l3);
        }
        *(uint4*)&Bs[0][bn][bseg]     = rb[0];
        *(uint4*)&Bs[0][bn][bseg + 8] = rb[1];
        *(uint4*)&Bs[1][bn][bseg]     = rb[2];
        *(uint4*)&Bs[1][bn][bseg + 8] = rb[3];
        __syncthreads();

        // ---- prefetch next phase (overlaps with MMAs below) ----
        if (p < 7) {
            int pn = p + 1;
            const float* A = (pn < 4) ? A1 : A2;
            const __nv_bfloat16* B = (pn < 4) ? B1 : B2;
            int k0 = (pn & 3) * 32;
            #pragma unroll
            for (int g = 0; g < 4; g++)
                ra[g] = aok[g] ? __ldg((const float4*)(A + (size_t)grow[g] * DD + k0 + ac))
                               : make_float4(0.f, 0.f, 0.f, 0.f);
            #pragma unroll
            for (int pl = 0; pl < 2; pl++) {
                const uint4* src = (const uint4*)(B + (size_t)pl * DD * DD +
                                                  (size_t)bn * DD + k0 + bseg);
                rb[pl * 2 + 0] = __ldg(src);
                rb[pl * 2 + 1] = __ldg(src + 1);
            }
        }

        // ---- MMAs on current chunk ----
        #pragma unroll
        for (int ks = 0; ks < 2; ks++) {
            int kk = ks * 16;
            uint32_t af[2][2][4];
            #pragma unroll
            for (int mi = 0; mi < 2; mi++)
                #pragma unroll
                for (int pl = 0; pl < 2; pl++) {
                    int row = wm + mi * 16;
                    af[mi][pl][0] = *(const uint32_t*)&As[pl][row + fr][kk + 2 * fc];
                    af[mi][pl][1] = *(const uint32_t*)&As[pl][row + fr + 8][kk + 2 * fc];
                    af[mi][pl][2] = *(const uint32_t*)&As[pl][row + fr][kk + 2 * fc + 8];
                    af[mi][pl][3] = *(const uint32_t*)&As[pl][row + fr + 8][kk + 2 * fc + 8];
                }
            uint32_t bf[8][2][2];
            #pragma unroll
            for (int ni = 0; ni < 8; ni++)
                #pragma unroll
                for (int pl = 0; pl < 2; pl++) {
                    int col = wn + ni * 8 + fr;
                    bf[ni][pl][0] = *(const uint32_t*)&Bs[pl][col][kk + 2 * fc];
                    bf[ni][pl][1] = *(const uint32_t*)&Bs[pl][col][kk + 2 * fc + 8];
                }
            #pragma unroll
            for (int mi = 0; mi < 2; mi++)
                #pragma unroll
                for (int ni = 0; ni < 8; ni++) {
                    MMA_BF16(acc[mi][ni], af[mi][0], bf[ni][0]);  // hi*hi
                    MMA_BF16(acc[mi][ni], af[mi][0], bf[ni][1]);  // hi*lo
                    MMA_BF16(acc[mi][ni], af[mi][1], bf[ni][0]);  // lo*hi
                }
        }
        __syncthreads();
    }

    // ---- epilogue: bias (+relu), store float2 per fragment row ----
    #pragma unroll
    for (int mi = 0; mi < 2; mi++) {
        #pragma unroll
        for (int ni = 0; ni < 8; ni++) {
            int col = wn + ni * 8 + 2 * fc;
            float bv0 = __ldg(&bias[col]);
            float bv1 = __ldg(&bias[col + 1]);
            int row0 = block_row + wm + mi * 16 + fr;
            float v0 = acc[mi][ni][0] + bv0;
            float v1 = acc[mi][ni][1] + bv1;
            float v2 = acc[mi][ni][2] + bv0;
            float v3 = acc[mi][ni][3] + bv1;
            if (relu) {
                v0 = fmaxf(v0, 0.f); v1 = fmaxf(v1, 0.f);
                v2 = fmaxf(v2, 0.f); v3 = fmaxf(v3, 0.f);
            }
            if (row0 < NN)
                *(float2*)&out[(size_t)row0 * DD + col] = make_float2(v0, v1);
            if (row0 + 8 < NN)
                *(float2*)&out[(size_t)(row0 + 8) * DD + col] = make_float2(v2, v3);
        }
    }
}

// ---------------- host launcher ----------------
extern "C" void kernel_launch(void* const* d_in, const int* in_sizes, int n_in,
                              void* d_out, int out_size) {
    const float* x   = (const float*)d_in[0];
    const void*  ei  = d_in[1];                 // int32 or int64 — probed on device
    const float* Wl0 = (const float*)d_in[2];
    const float* Wr0 = (const float*)d_in[3];
    const float* b0  = (const float*)d_in[4];
    const float* Wl1 = (const float*)d_in[5];
    const float* Wr1 = (const float*)d_in[6];
    const float* b1  = (const float*)d_in[7];
    float*       out = (float*)d_out;

    float* agg; cudaGetSymbolAddress((void**)&agg, g_agg);
    float* h;   cudaGetSymbolAddress((void**)&h,   g_h);
    int*   ptr; cudaGetSymbolAddress((void**)&ptr, g_ptr);
    __nv_bfloat16* Wbf; cudaGetSymbolAddress((void**)&Wbf, g_Wbf);
    const __nv_bfloat16* Bl0 = Wbf + (size_t)0 * 2 * DD * DD;
    const __nv_bfloat16* Br0 = Wbf + (size_t)1 * 2 * DD * DD;
    const __nv_bfloat16* Bl1 = Wbf + (size_t)2 * 2 * DD * DD;
    const __nv_bfloat16* Br1 = Wbf + (size_t)3 * 2 * DD * DD;

    // CSR build (dst-sorted) + weight prep + dtype probe, reused by both layers
    cudaMemsetAsync(ptr, 0, (size_t)PTRSZ * sizeof(int));
    k_pre<<<256, 256>>>(Wl0, Wr0, Wl1, Wr1, (const unsigned int*)ei);
    k_hist<<<(EE / 2 + 255) / 256, 256>>>(ei);
    k_scan1<<<SCAN_BLOCKS, 256>>>();
    k_scan2<<<1, 64>>>();
    k_scan3<<<(NP1 + 255) / 256, 256>>>();
    k_scatter<<<(EE / 2 + 255) / 256, 256>>>(ei);

    const int gemm_blocks = (NN + 127) / 128;
    const int agg_blocks  = (NN + 7) / 8;   // 8 warps per block

    // layer 0: h = relu(agg(x)@Wl0^T + x@Wr0^T + b0)
    k_agg<<<agg_blocks, 256>>>(x, agg);
    k_gemm<<<gemm_blocks, 256>>>(agg, x, Bl0, Br0, b0, h, 1);

    // layer 1: out = agg(h)@Wl1^T + h@Wr1^T + b1
    k_agg<<<agg_blocks, 256>>>(h, agg);
    k_gemm<<<gemm_blocks, 256>>>(agg, h, Bl1, Br1, b1, out, 0);
}

// round 16
// speedup vs baseline: 1.9450x; 1.0267x over previous
#include <cuda_runtime.h>
#include <cuda_bf16.h>
#include <cstdint>

#define NN 50000
#define EE 800000
#define DD 128
#define NP1 (NN + 1)
#define SCAN_BLOCKS 49             // ceil(50001/1024)
#define PTRSZ (SCAN_BLOCKS * 1024) // padded histogram/scan region (50176)

// ---------------- device scratch (no allocation allowed; statically zeroed) --
__device__ float g_agg[(size_t)NN * DD];      // aggregated features
__device__ float g_h[(size_t)NN * DD];        // hidden layer output
__device__ __align__(16) int g_ptr[PTRSZ + 8]; // histogram / in-place scan
__device__ int   g_ptrF[NP1];                 // final CSR offsets
__device__ int   g_cursor[NN];                // scatter cursors
__device__ int   g_src_sorted[EE];            // src ids sorted by dst
__device__ float g_inv_deg[NN];               // 1 / max(deg,1)
__device__ int   g_bsum[64];                  // scan block partials
// bf16 hi/lo weight planes: [mat(4)][plane(2)][n=128][k=128]
__device__ __nv_bfloat16 g_Wbf[4 * 2 * DD * DD];

// Per-block dtype probe: int64 ids < 2^31 -> odd 32-bit words all zero;
// int32 -> odd words are random node ids (zero w.p. 1/50000 each).
// 256 words => wrong-answer prob (1/50000)^256 ~= 0. Words 1..511 are
// in-bounds under both dtype interpretations.
__device__ __forceinline__ int probe_is32(const unsigned int* w) {
    int flag = (w[2 * threadIdx.x + 1] != 0u) ? 1 : 0;
    return __syncthreads_or(flag);
}

// ---------------- fused: weight prep + histogram (one kernel) ----------------
// grid 1563 x 256. All blocks: histogram (2 edges/thread). Blocks < 256 also
// convert one weight chunk to bf16 hi/lo planes (65536 elems total).
__global__ void k_ph(const float* __restrict__ Wl0, const float* __restrict__ Wr0,
                     const float* __restrict__ Wl1, const float* __restrict__ Wr1,
                     const void* __restrict__ eiv) {
    int is32 = probe_is32((const unsigned int*)eiv);
    int b = blockIdx.x, t = threadIdx.x;

    if (b < 256) {
        int i = b * 256 + t;
        int m = i >> 14;
        int rem = i & 16383;
        const float* W = (m == 0) ? Wl0 : (m == 1) ? Wr0 : (m == 2) ? Wl1 : Wr1;
        float v = W[rem];
        __nv_bfloat16 hi = __float2bfloat16(v);
        __nv_bfloat16 lo = __float2bfloat16(v - __bfloat162float(hi));
        g_Wbf[(size_t)(m * 2 + 0) * DD * DD + rem] = hi;
        g_Wbf[(size_t)(m * 2 + 1) * DD * DD + rem] = lo;
    }

    int e2 = (b * 256 + t) * 2;
    if (e2 < EE) {
        int d0, d1;
        if (is32) {
            const int2 dd = *(const int2*)((const int*)eiv + EE + e2);
            d0 = dd.x; d1 = dd.y;
        } else {
            const longlong2 dd = *(const longlong2*)((const long long*)eiv + EE + e2);
            d0 = (int)dd.x; d1 = (int)dd.y;
        }
        atomicAdd(&g_ptr[d0 + 1], 1);
        atomicAdd(&g_ptr[d1 + 1], 1);
    }
}

// ---- scan stage 1: per-block inclusive scan in place + block totals ---------
// 49 blocks x 256 threads x 4 elems (proven in R10).
__global__ void k_scan1() {
    __shared__ int wsum[8];
    int t = threadIdx.x, lane = t & 31, wp = t >> 5;
    int base = blockIdx.x * 1024 + t * 4;
    int4 v = *(const int4*)&g_ptr[base];
    v.y += v.x; v.z += v.y; v.w += v.z;
    int s = v.w;
    #pragma unroll
    for (int off = 1; off < 32; off <<= 1) {
        int n = __shfl_up_sync(0xffffffffu, s, off);
        if (lane >= off) s += n;
    }
    if (lane == 31) wsum[wp] = s;
    __syncthreads();
    if (t < 8) {
        int x = wsum[t];
        #pragma unroll
        for (int off = 1; off < 8; off <<= 1) {
            int n = __shfl_up_sync(0xffu, x, off);
            if (t >= off) x += n;
        }
        wsum[t] = x;
    }
    __syncthreads();
    int add = (wp ? wsum[wp - 1] : 0) + (s - v.w);
    v.x += add; v.y += add; v.z += add; v.w += add;
    *(int4*)&g_ptr[base] = v;
    if (t == 255) g_bsum[blockIdx.x] = v.w;
}

// ---- scan stage 2: carries (computed redundantly per block) + finalize ------
// Each block scans the 49 block totals in shared (naive Hillis-Steele, proven
// pattern), then writes final offsets + inv_deg + cursor. Grid 196 x 256.
__global__ void k_scan3() {
    __shared__ int sh[64];
    int t = threadIdx.x;
    if (t < 64) sh[t] = (t < SCAN_BLOCKS) ? g_bsum[t] : 0;
    __syncthreads();
    #pragma unroll
    for (int off = 1; off < 64; off <<= 1) {
        int add = (t < 64 && t >= off) ? sh[t - off] : 0;
        __syncthreads();
        if (t < 64) sh[t] += add;
        __syncthreads();
    }
    int idx = blockIdx.x * 256 + t;
    if (idx >= NP1) return;
    int b0 = idx >> 10;
    int fin = g_ptr[idx] + (b0 ? sh[b0 - 1] : 0);
    g_ptrF[idx] = fin;
    if (idx < NN) {
        int b1 = (idx + 1) >> 10;
        int fin1 = g_ptr[idx + 1] + (b1 ? sh[b1 - 1] : 0);
        int d = fin1 - fin;
        g_inv_deg[idx] = 1.0f / (float)max(d, 1);
        g_cursor[idx] = fin;
    }
}

// ---------------- scatter + reset scratch for next replay --------------------
__global__ void k_scatter(const void* __restrict__ eiv) {
    int is32 = probe_is32((const unsigned int*)eiv);
    int gid = blockIdx.x * 256 + threadIdx.x;

    // reset histogram region for the next graph replay (int4 = 16B aligned)
    if (gid < (PTRSZ + 8) / 4) *(int4*)&g_ptr[gid * 4] = make_int4(0, 0, 0, 0);

    int e2 = gid * 2;
    if (e2 >= EE) return;
    int s0, s1, d0, d1;
    if (is32) {
        const int* p = (const int*)eiv;
        const int2 ss = *(const int2*)(p + e2);
        const int2 dd = *(const int2*)(p + EE + e2);
        s0 = ss.x; s1 = ss.y; d0 = dd.x; d1 = dd.y;
    } else {
        const long long* p = (const long long*)eiv;
        const longlong2 ss = *(const longlong2*)(p + e2);
        const longlong2 dd = *(const longlong2*)(p + EE + e2);
        s0 = (int)ss.x; s1 = (int)ss.y; d0 = (int)dd.x; d1 = (int)dd.y;
    }
    int p0 = atomicAdd(&g_cursor[d0], 1);
    g_src_sorted[p0] = s0;
    int p1 = atomicAdd(&g_cursor[d1], 1);
    g_src_sorted[p1] = s1;
}

// ---------------- segment-mean aggregation: one warp per dst node ------------
__global__ void k_agg(const float* __restrict__ in, float* __restrict__ out) {
    int w = (blockIdx.x * blockDim.x + threadIdx.x) >> 5;
    if (w >= NN) return;
    int lane = threadIdx.x & 31;
    int beg = g_ptrF[w], end = g_ptrF[w + 1];
    float4 acc = make_float4(0.f, 0.f, 0.f, 0.f);
    int e = beg;
    for (; e + 3 < end; e += 4) {
        int s0 = g_src_sorted[e];
        int s1 = g_src_sorted[e + 1];
        int s2 = g_src_sorted[e + 2];
        int s3 = g_src_sorted[e + 3];
        float4 a = __ldg((const float4*)(in + (size_t)s0 * DD) + lane);
        float4 b = __ldg((const float4*)(in + (size_t)s1 * DD) + lane);
        float4 c = __ldg((const float4*)(in + (size_t)s2 * DD) + lane);
        float4 d = __ldg((const float4*)(in + (size_t)s3 * DD) + lane);
        acc.x += (a.x + b.x) + (c.x + d.x);
        acc.y += (a.y + b.y) + (c.y + d.y);
        acc.z += (a.z + b.z) + (c.z + d.z);
        acc.w += (a.w + b.w) + (c.w + d.w);
    }
    for (; e < end; e++) {
        int s0 = g_src_sorted[e];
        float4 a = __ldg((const float4*)(in + (size_t)s0 * DD) + lane);
        acc.x += a.x; acc.y += a.y; acc.z += a.z; acc.w += a.w;
    }
    float inv = g_inv_deg[w];
    float4 r = make_float4(acc.x * inv, acc.y * inv, acc.z * inv, acc.w * inv);
    *((float4*)(out + (size_t)w * DD) + lane) = r;
}

// ---------------- tensor-core dual GEMM with bf16 hi/lo split ----------------
// out = A1@B1^T + A2@B2^T + bias (optional relu); B given as [o][k] (= W).
// Block 128x128, 8 warps (4m x 2n), warp tile 32x64, mma.m16n8k16.row.col.
// fp32 value v = hi + lo (bf16); product via 3 MMAs (hihi + hilo + lohi).
// One-phase register prefetch: chunk p+1 global loads overlap chunk p MMAs.
#define MMA_BF16(acc, a, b)                                              \
    asm volatile(                                                        \
        "mma.sync.aligned.m16n8k16.row.col.f32.bf16.bf16.f32 "           \
        "{%0,%1,%2,%3}, {%4,%5,%6,%7}, {%8,%9}, {%0,%1,%2,%3};"          \
        : "+f"(acc[0]), "+f"(acc[1]), "+f"(acc[2]), "+f"(acc[3])         \
        : "r"(a[0]), "r"(a[1]), "r"(a[2]), "r"(a[3]), "r"(b[0]), "r"(b[1]))

__global__ void __launch_bounds__(256)
k_gemm(const float* __restrict__ A1, const float* __restrict__ A2,
       const __nv_bfloat16* __restrict__ B1,   // [2][128][128] hi/lo planes
       const __nv_bfloat16* __restrict__ B2,
       const float* __restrict__ bias, float* __restrict__ out, int relu) {
    __shared__ __nv_bfloat16 As[2][128][40];   // [plane][m][k] pad 40 (conflict-free)
    __shared__ __nv_bfloat16 Bs[2][128][40];   // [plane][n][k]

    int t = threadIdx.x;
    int block_row = blockIdx.x * 128;
    int wid = t >> 5, lane = t & 31;
    int wm = (wid & 3) * 32;                   // warp row offset
    int wn = (wid >> 2) * 64;                  // warp col offset
    int fr = lane >> 2, fc = lane & 3;

    float acc[2][8][4];
    #pragma unroll
    for (int mi = 0; mi < 2; mi++)
        #pragma unroll
        for (int ni = 0; ni < 8; ni++)
            #pragma unroll
            for (int q = 0; q < 4; q++) acc[mi][ni][q] = 0.f;

    int ar = t >> 3, ac = (t & 7) * 4;
    int bn = t >> 1, bseg = (t & 1) * 16;

    int grow[4]; bool aok[4];
    #pragma unroll
    for (int g = 0; g < 4; g++) {
        grow[g] = block_row + ar + g * 32;
        aok[g] = grow[g] < NN;
    }

    float4 ra[4];
    uint4  rb[4];

    #pragma unroll
    for (int g = 0; g < 4; g++)
        ra[g] = aok[g] ? __ldg((const float4*)(A1 + (size_t)grow[g] * DD + ac))
                       : make_float4(0.f, 0.f, 0.f, 0.f);
    #pragma unroll
    for (int pl = 0; pl < 2; pl++) {
        const uint4* src = (const uint4*)(B1 + (size_t)pl * DD * DD + (size_t)bn * DD + bseg);
        rb[pl * 2 + 0] = __ldg(src);
        rb[pl * 2 + 1] = __ldg(src + 1);
    }

    #pragma unroll 1
    for (int p = 0; p < 8; p++) {
        #pragma unroll
        for (int g = 0; g < 4; g++) {
            int row = ar + g * 32;
            float4 v = ra[g];
            __nv_bfloat16 h0 = __float2bfloat16(v.x);
            __nv_bfloat16 h1 = __float2bfloat16(v.y);
            __nv_bfloat16 h2 = __float2bfloat16(v.z);
            __nv_bfloat16 h3 = __float2bfloat16(v.w);
            __nv_bfloat16 l0 = __float2bfloat16(v.x - __bfloat162float(h0));
            __nv_bfloat16 l1 = __float2bfloat16(v.y - __bfloat162float(h1));
            __nv_bfloat16 l2 = __float2bfloat16(v.z - __bfloat162float(h2));
            __nv_bfloat16 l3 = __float2bfloat16(v.w - __bfloat162float(h3));
            *(__nv_bfloat162*)&As[0][row][ac]     = __halves2bfloat162(h0, h1);
            *(__nv_bfloat162*)&As[0][row][ac + 2] = __halves2bfloat162(h2, h3);
            *(__nv_bfloat162*)&As[1][row][ac]     = __halves2bfloat162(l0, l1);
            *(__nv_bfloat162*)&As[1][row][ac + 2] = __halves2bfloat162(l2, l3);
        }
        *(uint4*)&Bs[0][bn][bseg]     = rb[0];
        *(uint4*)&Bs[0][bn][bseg + 8] = rb[1];
        *(uint4*)&Bs[1][bn][bseg]     = rb[2];
        *(uint4*)&Bs[1][bn][bseg + 8] = rb[3];
        __syncthreads();

        if (p < 7) {
            int pn = p + 1;
            const float* A = (pn < 4) ? A1 : A2;
            const __nv_bfloat16* B = (pn < 4) ? B1 : B2;
            int k0 = (pn & 3) * 32;
            #pragma unroll
            for (int g = 0; g < 4; g++)
                ra[g] = aok[g] ? __ldg((const float4*)(A + (size_t)grow[g] * DD + k0 + ac))
                               : make_float4(0.f, 0.f, 0.f, 0.f);
            #pragma unroll
            for (int pl = 0; pl < 2; pl++) {
                const uint4* src = (const uint4*)(B + (size_t)pl * DD * DD +
                                                  (size_t)bn * DD + k0 + bseg);
                rb[pl * 2 + 0] = __ldg(src);
                rb[pl * 2 + 1] = __ldg(src + 1);
            }
        }

        #pragma unroll
        for (int ks = 0; ks < 2; ks++) {
            int kk = ks * 16;
            uint32_t af[2][2][4];
            #pragma unroll
            for (int mi = 0; mi < 2; mi++)
                #pragma unroll
                for (int pl = 0; pl < 2; pl++) {
                    int row = wm + mi * 16;
                    af[mi][pl][0] = *(const uint32_t*)&As[pl][row + fr][kk + 2 * fc];
                    af[mi][pl][1] = *(const uint32_t*)&As[pl][row + fr + 8][kk + 2 * fc];
                    af[mi][pl][2] = *(const uint32_t*)&As[pl][row + fr][kk + 2 * fc + 8];
                    af[mi][pl][3] = *(const uint32_t*)&As[pl][row + fr + 8][kk + 2 * fc + 8];
                }
            uint32_t bf[8][2][2];
            #pragma unroll
            for (int ni = 0; ni < 8; ni++)
                #pragma unroll
                for (int pl = 0; pl < 2; pl++) {
                    int col = wn + ni * 8 + fr;
                    bf[ni][pl][0] = *(const uint32_t*)&Bs[pl][col][kk + 2 * fc];
                    bf[ni][pl][1] = *(const uint32_t*)&Bs[pl][col][kk + 2 * fc + 8];
                }
            #pragma unroll
            for (int mi = 0; mi < 2; mi++)
                #pragma unroll
                for (int ni = 0; ni < 8; ni++) {
                    MMA_BF16(acc[mi][ni], af[mi][0], bf[ni][0]);  // hi*hi
                    MMA_BF16(acc[mi][ni], af[mi][0], bf[ni][1]);  // hi*lo
                    MMA_BF16(acc[mi][ni], af[mi][1], bf[ni][0]);  // lo*hi
                }
        }
        __syncthreads();
    }

    #pragma unroll
    for (int mi = 0; mi < 2; mi++) {
        #pragma unroll
        for (int ni = 0; ni < 8; ni++) {
            int col = wn + ni * 8 + 2 * fc;
            float bv0 = __ldg(&bias[col]);
            float bv1 = __ldg(&bias[col + 1]);
            int row0 = block_row + wm + mi * 16 + fr;
            float v0 = acc[mi][ni][0] + bv0;
            float v1 = acc[mi][ni][1] + bv1;
            float v2 = acc[mi][ni][2] + bv0;
            float v3 = acc[mi][ni][3] + bv1;
            if (relu) {
                v0 = fmaxf(v0, 0.f); v1 = fmaxf(v1, 0.f);
                v2 = fmaxf(v2, 0.f); v3 = fmaxf(v3, 0.f);
            }
            if (row0 < NN)
                *(float2*)&out[(size_t)row0 * DD + col] = make_float2(v0, v1);
            if (row0 + 8 < NN)
                *(float2*)&out[(size_t)(row0 + 8) * DD + col] = make_float2(v2, v3);
        }
    }
}

// ---------------- host launcher ----------------
extern "C" void kernel_launch(void* const* d_in, const int* in_sizes, int n_in,
                              void* d_out, int out_size) {
    const float* x   = (const float*)d_in[0];
    const void*  ei  = d_in[1];                 // int32 or int64 — probed on device
    const float* Wl0 = (const float*)d_in[2];
    const float* Wr0 = (const float*)d_in[3];
    const float* b0  = (const float*)d_in[4];
    const float* Wl1 = (const float*)d_in[5];
    const float* Wr1 = (const float*)d_in[6];
    const float* b1  = (const float*)d_in[7];
    float*       out = (float*)d_out;

    float* agg; cudaGetSymbolAddress((void**)&agg, g_agg);
    float* h;   cudaGetSymbolAddress((void**)&h,   g_h);
    __nv_bfloat16* Wbf; cudaGetSymbolAddress((void**)&Wbf, g_Wbf);
    const __nv_bfloat16* Bl0 = Wbf + (size_t)0 * 2 * DD * DD;
    const __nv_bfloat16* Br0 = Wbf + (size_t)1 * 2 * DD * DD;
    const __nv_bfloat16* Bl1 = Wbf + (size_t)2 * 2 * DD * DD;
    const __nv_bfloat16* Br1 = Wbf + (size_t)3 * 2 * DD * DD;

    const int eb = (EE / 2 + 255) / 256;    // 1563

    // CSR build (4 nodes): hist+weightprep, scan1, scan3 (carries inline),
    // scatter+reset
    k_ph<<<eb, 256>>>(Wl0, Wr0, Wl1, Wr1, ei);
    k_scan1<<<SCAN_BLOCKS, 256>>>();
    k_scan3<<<(NP1 + 255) / 256, 256>>>();
    k_scatter<<<eb, 256>>>(ei);

    const int gemm_blocks = (NN + 127) / 128;
    const int agg_blocks  = (NN + 7) / 8;   // 8 warps per block

    // layer 0: h = relu(agg(x)@Wl0^T + x@Wr0^T + b0)
    k_agg<<<agg_blocks, 256>>>(x, agg);
    k_gemm<<<gemm_blocks, 256>>>(agg, x, Bl0, Br0, b0, h, 1);

    // layer 1: out = agg(h)@Wl1^T + h@Wr1^T + b1
    k_agg<<<agg_blocks, 256>>>(h, agg);
    k_gemm<<<gemm_blocks, 256>>>(agg, h, Bl1, Br1, b1, out, 0);
}